// round 3
// baseline (speedup 1.0000x reference)
#include <cuda_runtime.h>
#include <cstdio>

#define B_   8
#define NQ_  75
#define NS_  5
#define NG_  4
#define NF_  49
#define C_   64

#define ROWS_ 294
#define STR_  68           // smem row stride in floats (8B-aligned rows)
#define NT2_  320

__device__ float g_p1[B_ * NQ_ * NS_ * NG_];
__device__ float g_p2[B_ * NQ_ * NS_ * NG_];
__device__ float g_kss[B_ * NS_ * NG_ * NF_ * NF_];   // [bid160][i*49+j]

__device__ __forceinline__ float multi_gauss(float d2) {
    d2 = fmaxf(d2, 0.0f);
    float t  = __expf(-0.125f * d2);
    float t2 = t * t;
    float t4 = t2 * t2;
    float t8 = t4 * t4;
    float t16 = t8 * t8;
    return t + t2 + t4 + t8 + t16;
}

__device__ __forceinline__ void fma2(unsigned long long& d,
                                     unsigned long long a, unsigned long long b) {
    asm("fma.rn.f32x2 %0, %1, %2, %0;" : "+l"(d) : "l"(a), "l"(b));
}

__device__ __forceinline__ float f32x2_sum(unsigned long long v) {
    return __uint_as_float((unsigned)v) + __uint_as_float((unsigned)(v >> 32));
}

// ---------------------------------------------------------------------------
// k1a: per (b,s,g) -> Kss (49x49) via 7x7 f32x2 micro-tiles -> g_kss
// ---------------------------------------------------------------------------
__global__ __launch_bounds__(64) void k1a_kss(const float* __restrict__ sup) {
    __shared__ float sraw[49 * STR_];
    __shared__ float ssq[52];

    int bid = blockIdx.x;              // 0..159 = (b*5+s)*4+g
    int tid = threadIdx.x;

    const float* sb = sup + (size_t)bid * 49 * 64;
    for (int idx = tid; idx < 49 * 16; idx += 64) {
        int r = idx >> 4, c4 = idx & 15;
        *(float4*)(sraw + r * STR_ + c4 * 4) = *(const float4*)(sb + r * 64 + c4 * 4);
    }
    __syncthreads();

    if (tid < 49) {
        const float2* xr = (const float2*)(sraw + tid * STR_);
        float a0 = 0.f, a1 = 0.f;
        #pragma unroll
        for (int c = 0; c < 32; c++) { float2 x = xr[c]; a0 = fmaf(x.x, x.x, a0); a1 = fmaf(x.y, x.y, a1); }
        ssq[tid] = a0 + a1;
    }
    __syncthreads();

    if (tid < 49) {
        int it = tid / 7, jt = tid - it * 7;
        unsigned long long acc2[49];
        #pragma unroll
        for (int k = 0; k < 49; k++) acc2[k] = 0ull;
        const unsigned long long* A  = (const unsigned long long*)(sraw + it * 7 * STR_);
        const unsigned long long* Bm = (const unsigned long long*)(sraw + jt * 7 * STR_);
        #pragma unroll 1
        for (int c2 = 0; c2 < 32; c2++) {
            unsigned long long a2[7], b2[7];
            #pragma unroll
            for (int k = 0; k < 7; k++) a2[k] = A[k * (STR_ / 2) + c2];
            #pragma unroll
            for (int k = 0; k < 7; k++) b2[k] = Bm[k * (STR_ / 2) + c2];
            #pragma unroll
            for (int ii = 0; ii < 7; ii++)
                #pragma unroll
                for (int jj = 0; jj < 7; jj++)
                    fma2(acc2[ii * 7 + jj], a2[ii], b2[jj]);
        }
        float* kout = g_kss + (size_t)bid * 2401;
        #pragma unroll
        for (int ii = 0; ii < 7; ii++) {
            float ri = ssq[it * 7 + ii];
            #pragma unroll
            for (int jj = 0; jj < 7; jj++) {
                float dot = f32x2_sum(acc2[ii * 7 + jj]);
                float d2 = ri + ssq[jt * 7 + jj] - 2.0f * dot;
                kout[(it * 7 + ii) * 49 + jt * 7 + jj] = multi_gauss(d2);
            }
        }
    }
}

// ---------------------------------------------------------------------------
// k1b: per (b,s,g,vchunk of 15) -> beta^T Kss beta, Kss from g_kss (L2-hot)
// ---------------------------------------------------------------------------
__global__ __launch_bounds__(256) void k1b_bilinear(const float* __restrict__ beta) {
    __shared__ float kss[49 * 50];
    __shared__ float betas[15 * 50];
    __shared__ float scr[735];

    int bid = blockIdx.x;              // 0..799
    int g = bid & 3;
    int rest = bid >> 2;
    int s = rest % NS_;  rest /= NS_;
    int vt = rest % 5;
    int b = rest / 5;
    int tid = threadIdx.x;

    int bid160 = (b * NS_ + s) * NG_ + g;
    const float* ksrc = g_kss + (size_t)bid160 * 2401;
    for (int idx = tid; idx < 2401; idx += 256) {
        int i = idx / 49, j = idx - i * 49;
        kss[i * 50 + j] = ksrc[idx];
    }
    for (int idx = tid; idx < 15 * 49; idx += 256) {
        int vv = idx / 49, j = idx - vv * 49;
        int v = vt * 15 + vv;
        size_t off = ((size_t)((b * NQ_ + v) * NS_ + s) * NG_ + g) * 49 + j;
        betas[vv * 50 + j] = beta[off];
    }
    __syncthreads();

    for (int t = tid; t < 735; t += 256) {
        int vv = t / 49, i = t - vv * 49;
        const float2* kr = (const float2*)(kss + i * 50);
        const float2* bv = (const float2*)(betas + vv * 50);
        float r0 = 0.f, r1 = 0.f;
        #pragma unroll
        for (int c = 0; c < 24; c++) {
            float2 kk = kr[c], bb = bv[c];
            r0 = fmaf(kk.x, bb.x, r0);
            r1 = fmaf(kk.y, bb.y, r1);
        }
        float r = r0 + r1 + kss[i * 50 + 48] * betas[vv * 50 + 48];
        scr[t] = betas[vv * 50 + i] * r;
    }
    __syncthreads();

    if (tid < 15) {
        float acc = 0.f;
        #pragma unroll
        for (int k = 0; k < 49; k++) acc += scr[tid * 49 + k];
        int v = vt * 15 + tid;
        g_p1[((b * NQ_ + v) * NS_ + s) * NG_ + g] = acc;
    }
}

// ---------------------------------------------------------------------------
// k2: per (b,v,g). 294x49 dots via 7x7 micro-tiles with packed fma.rn.f32x2.
// ---------------------------------------------------------------------------
__global__ __launch_bounds__(NT2_, 1) void k2_main(const float* __restrict__ sup,
                                                   const float* __restrict__ qry,
                                                   const float* __restrict__ beta,
                                                   const float* __restrict__ gamma) {
    extern __shared__ float sm[];
    float* xs   = sm;                     // 294*68
    float* rsq  = xs + ROWS_ * STR_;      // 296
    float* bet  = rsq + 296;              // 245
    float* gam  = bet + 245;              // 245
    float* scr  = gam + 245;              // 245
    float* scrq = scr + 245;              // 245
    float* red  = scrq + 245;             // 16

    int bid = blockIdx.x;                 // 0..2399
    int g = bid & 3;
    int bv = bid >> 2;
    int b = bv / NQ_;
    int tid = threadIdx.x;

    const float* supb = sup + (size_t)(b * (NS_ * NG_) + g) * 49 * 64;
    const float* qryb = qry + ((size_t)bv * NG_ + g) * 49 * 64;

    for (int idx = tid; idx < ROWS_ * 16; idx += NT2_) {
        int r = idx >> 4, c4 = idx & 15;
        float4 val;
        if (r < 245) {
            int s = r / 49;
            int i = r - s * 49;
            val = *(const float4*)(supb + (size_t)s * (NG_ * 49 * 64) + i * 64 + c4 * 4);
        } else {
            val = *(const float4*)(qryb + (r - 245) * 64 + c4 * 4);
        }
        *(float4*)(xs + r * STR_ + c4 * 4) = val;
    }
    for (int idx = tid; idx < NS_ * 49; idx += NT2_) {
        int s = idx / 49, j = idx - s * 49;
        size_t off = ((size_t)(bv * NS_ + s) * NG_ + g) * 49 + j;
        bet[idx] = beta[off];
        gam[idx] = gamma[off];
    }
    __syncthreads();

    for (int r = tid; r < ROWS_; r += NT2_) {
        const float2* xr = (const float2*)(xs + r * STR_);
        float a0 = 0.f, a1 = 0.f;
        #pragma unroll
        for (int c = 0; c < 32; c++) { float2 x = xr[c]; a0 = fmaf(x.x, x.x, a0); a1 = fmaf(x.y, x.y, a1); }
        rsq[r] = a0 + a1;
    }
    __syncthreads();

    bool active = (tid < ROWS_);
    int it = tid / 7;
    int jt = tid - it * 7;

    if (active) {
        unsigned long long acc2[49];
        #pragma unroll
        for (int k = 0; k < 49; k++) acc2[k] = 0ull;

        const unsigned long long* A  = (const unsigned long long*)(xs + it * 7 * STR_);
        const unsigned long long* Bm = (const unsigned long long*)(xs + (245 + jt * 7) * STR_);
        #pragma unroll 1
        for (int c2 = 0; c2 < 32; c2++) {
            unsigned long long a2[7], b2[7];
            #pragma unroll
            for (int k = 0; k < 7; k++) a2[k] = A[k * (STR_ / 2) + c2];
            #pragma unroll
            for (int k = 0; k < 7; k++) b2[k] = Bm[k * (STR_ / 2) + c2];
            #pragma unroll
            for (int ii = 0; ii < 7; ii++)
                #pragma unroll
                for (int jj = 0; jj < 7; jj++)
                    fma2(acc2[ii * 7 + jj], a2[ii], b2[jj]);
        }

        float kv[49];
        float qsq[7];
        int jbase = jt * 7;
        #pragma unroll
        for (int jj = 0; jj < 7; jj++) qsq[jj] = rsq[245 + jbase + jj];
        #pragma unroll
        for (int ii = 0; ii < 7; ii++) {
            float ri = rsq[it * 7 + ii];
            #pragma unroll
            for (int jj = 0; jj < 7; jj++) {
                float dot = f32x2_sum(acc2[ii * 7 + jj]);
                float d2 = ri + qsq[jj] - 2.0f * dot;
                kv[ii * 7 + jj] = multi_gauss(d2);
            }
        }

        if (it < 35) {
            int s = it / 7;
            int i0 = it * 7 - s * 49;
            const float* gs = gam + s * 49 + jbase;
            const float* bs = bet + s * 49 + i0;
            float partial = 0.0f;
            #pragma unroll
            for (int ii = 0; ii < 7; ii++) {
                float rowsum = 0.0f;
                #pragma unroll
                for (int jj = 0; jj < 7; jj++) rowsum = fmaf(kv[ii * 7 + jj], gs[jj], rowsum);
                partial = fmaf(bs[ii], rowsum, partial);
            }
            scr[tid] = partial;
        } else {
            int q0 = it * 7 - 245;
            int qt = tid - 245;
            #pragma unroll
            for (int s = 0; s < 5; s++) {
                const float* gs = gam + s * 49;
                float pq = 0.0f;
                #pragma unroll
                for (int ii = 0; ii < 7; ii++) {
                    float rowsum = 0.0f;
                    #pragma unroll
                    for (int jj = 0; jj < 7; jj++) rowsum = fmaf(kv[ii * 7 + jj], gs[jbase + jj], rowsum);
                    pq = fmaf(gs[q0 + ii], rowsum, pq);
                }
                scrq[s * 49 + qt] = pq;
            }
        }
    }
    __syncthreads();

    if (tid < 10) {
        int s = tid % 5;
        const float* src = (tid < 5) ? (scr + s * 49) : (scrq + s * 49);
        float acc = 0.f;
        #pragma unroll
        for (int k = 0; k < 49; k++) acc += src[k];
        red[tid] = acc;
    }
    __syncthreads();

    if (tid < NS_) {
        int idx = (bv * NS_ + tid) * NG_ + g;
        g_p2[idx] = red[5 + tid] - 2.0f * red[tid];
    }
}

__global__ void k3_reduce(float* __restrict__ out) {
    int o = blockIdx.x * blockDim.x + threadIdx.x;
    if (o < B_ * NQ_ * NS_) {
        float s = 0.0f;
        #pragma unroll
        for (int g = 0; g < NG_; g++) s += g_p1[o * NG_ + g] + g_p2[o * NG_ + g];
        out[o] = 0.25f * s;
    }
}

extern "C" void kernel_launch(void* const* d_in, const int* in_sizes, int n_in,
                              void* d_out, int out_size) {
    const float* sup   = (const float*)d_in[0];
    const float* qry   = (const float*)d_in[1];
    const float* beta  = (const float*)d_in[2];
    const float* gamma = (const float*)d_in[3];
    float* out = (float*)d_out;

    const int smem2 = (ROWS_ * STR_ + 296 + 245 * 4 + 16) * (int)sizeof(float);
    static bool configured = false;
    if (!configured) {
        cudaFuncSetAttribute(k2_main, cudaFuncAttributeMaxDynamicSharedMemorySize, smem2);
        configured = true;
    }

    k1a_kss<<<B_ * NS_ * NG_, 64>>>(sup);
    k1b_bilinear<<<B_ * NS_ * NG_ * 5, 256>>>(beta);
    k2_main<<<B_ * NQ_ * NG_, NT2_, smem2>>>(sup, qry, beta, gamma);
    k3_reduce<<<(B_ * NQ_ * NS_ + 255) / 256, 256>>>(out);
}

// round 4
// speedup vs baseline: 1.2578x; 1.2578x over previous
#include <cuda_runtime.h>
#include <cstdio>

#define B_   8
#define NQ_  75
#define NS_  5
#define NG_  4
#define NF_  49
#define C_   64

#define ROWS_ 294
#define STR_  68
#define NT2_  320

__device__ float g_p1[B_ * NQ_ * NS_ * NG_];
__device__ float g_p2[B_ * NQ_ * NS_ * NG_];
__device__ float g_kss[B_ * NS_ * NG_ * NF_ * NF_];

__device__ __forceinline__ float multi_gauss(float d2) {
    d2 = fmaxf(d2, 0.0f);
    float t  = __expf(-0.125f * d2);
    float t2 = t * t;
    float t4 = t2 * t2;
    float t8 = t4 * t4;
    float t16 = t8 * t8;
    return t + t2 + t4 + t8 + t16;
}

// ---------------------------------------------------------------------------
// k1a: per (b,s,g) -> Kss (49x49) once -> g_kss (scalar FFMA micro-tiles)
// ---------------------------------------------------------------------------
__global__ __launch_bounds__(64) void k1a_kss(const float* __restrict__ sup) {
    __shared__ float sraw[49 * STR_];
    __shared__ float ssq[52];

    int bid = blockIdx.x;              // 0..159 = (b*5+s)*4+g
    int tid = threadIdx.x;

    const float* sb = sup + (size_t)bid * 49 * 64;
    for (int idx = tid; idx < 49 * 16; idx += 64) {
        int r = idx >> 4, c4 = idx & 15;
        *(float4*)(sraw + r * STR_ + c4 * 4) = *(const float4*)(sb + r * 64 + c4 * 4);
    }
    __syncthreads();

    if (tid < 49) {
        const float2* xr = (const float2*)(sraw + tid * STR_);
        float a0 = 0.f, a1 = 0.f;
        #pragma unroll
        for (int c = 0; c < 32; c++) { float2 x = xr[c]; a0 = fmaf(x.x, x.x, a0); a1 = fmaf(x.y, x.y, a1); }
        ssq[tid] = a0 + a1;
    }
    __syncthreads();

    if (tid < 49) {
        int it = tid / 7, jt = tid - it * 7;
        float acc[49];
        #pragma unroll
        for (int k = 0; k < 49; k++) acc[k] = 0.f;
        const float2* A  = (const float2*)(sraw + it * 7 * STR_);
        const float2* Bm = (const float2*)(sraw + jt * 7 * STR_);
        #pragma unroll 1
        for (int c2 = 0; c2 < 32; c2++) {
            float2 a[7], bb[7];
            #pragma unroll
            for (int k = 0; k < 7; k++) a[k]  = A[k * (STR_ / 2) + c2];
            #pragma unroll
            for (int k = 0; k < 7; k++) bb[k] = Bm[k * (STR_ / 2) + c2];
            #pragma unroll
            for (int ii = 0; ii < 7; ii++)
                #pragma unroll
                for (int jj = 0; jj < 7; jj++) {
                    acc[ii * 7 + jj] = fmaf(a[ii].x, bb[jj].x, acc[ii * 7 + jj]);
                    acc[ii * 7 + jj] = fmaf(a[ii].y, bb[jj].y, acc[ii * 7 + jj]);
                }
        }
        float* kout = g_kss + (size_t)bid * 2401;
        #pragma unroll
        for (int ii = 0; ii < 7; ii++) {
            float ri = ssq[it * 7 + ii];
            #pragma unroll
            for (int jj = 0; jj < 7; jj++) {
                float d2 = ri + ssq[jt * 7 + jj] - 2.0f * acc[ii * 7 + jj];
                kout[(it * 7 + ii) * 49 + jt * 7 + jj] = multi_gauss(d2);
            }
        }
    }
}

// ---------------------------------------------------------------------------
// k1b: per (b,s,g,vchunk of 15) -> beta^T Kss beta, Kss from g_kss (L2-hot)
// ---------------------------------------------------------------------------
__global__ __launch_bounds__(256) void k1b_bilinear(const float* __restrict__ beta) {
    __shared__ float kss[49 * 50];
    __shared__ float betas[15 * 50];
    __shared__ float scr[735];

    int bid = blockIdx.x;              // 0..799
    int g = bid & 3;
    int rest = bid >> 2;
    int s = rest % NS_;  rest /= NS_;
    int vt = rest % 5;
    int b = rest / 5;
    int tid = threadIdx.x;

    int bid160 = (b * NS_ + s) * NG_ + g;
    const float* ksrc = g_kss + (size_t)bid160 * 2401;
    for (int idx = tid; idx < 2401; idx += 256) {
        int i = idx / 49, j = idx - i * 49;
        kss[i * 50 + j] = ksrc[idx];
    }
    for (int idx = tid; idx < 15 * 49; idx += 256) {
        int vv = idx / 49, j = idx - vv * 49;
        int v = vt * 15 + vv;
        size_t off = ((size_t)((b * NQ_ + v) * NS_ + s) * NG_ + g) * 49 + j;
        betas[vv * 50 + j] = beta[off];
    }
    __syncthreads();

    for (int t = tid; t < 735; t += 256) {
        int vv = t / 49, i = t - vv * 49;
        const float2* kr = (const float2*)(kss + i * 50);
        const float2* bv = (const float2*)(betas + vv * 50);
        float r0 = 0.f, r1 = 0.f;
        #pragma unroll
        for (int c = 0; c < 24; c++) {
            float2 kk = kr[c], bb = bv[c];
            r0 = fmaf(kk.x, bb.x, r0);
            r1 = fmaf(kk.y, bb.y, r1);
        }
        float r = r0 + r1 + kss[i * 50 + 48] * betas[vv * 50 + 48];
        scr[t] = betas[vv * 50 + i] * r;
    }
    __syncthreads();

    if (tid < 15) {
        float acc = 0.f;
        #pragma unroll
        for (int k = 0; k < 49; k++) acc += scr[tid * 49 + k];
        int v = vt * 15 + tid;
        g_p1[((b * NQ_ + v) * NS_ + s) * NG_ + g] = acc;
    }
}

// ---------------------------------------------------------------------------
// k2: per (b,v,g). 294x49 dots via 7x7 scalar-FFMA micro-tiles (2 CTA/SM).
// ---------------------------------------------------------------------------
__global__ __launch_bounds__(NT2_, 2) void k2_main(const float* __restrict__ sup,
                                                   const float* __restrict__ qry,
                                                   const float* __restrict__ beta,
                                                   const float* __restrict__ gamma) {
    extern __shared__ float sm[];
    float* xs   = sm;                     // 294*68
    float* rsq  = xs + ROWS_ * STR_;      // 296
    float* bet  = rsq + 296;              // 245
    float* gam  = bet + 245;              // 245
    float* scr  = gam + 245;              // 245
    float* scrq = scr + 245;              // 245
    float* red  = scrq + 245;             // 16

    int bid = blockIdx.x;                 // 0..2399
    int g = bid & 3;
    int bv = bid >> 2;
    int b = bv / NQ_;
    int tid = threadIdx.x;

    const float* supb = sup + (size_t)(b * (NS_ * NG_) + g) * 49 * 64;
    const float* qryb = qry + ((size_t)bv * NG_ + g) * 49 * 64;

    for (int idx = tid; idx < ROWS_ * 16; idx += NT2_) {
        int r = idx >> 4, c4 = idx & 15;
        float4 val;
        if (r < 245) {
            int s = r / 49;
            int i = r - s * 49;
            val = *(const float4*)(supb + (size_t)s * (NG_ * 49 * 64) + i * 64 + c4 * 4);
        } else {
            val = *(const float4*)(qryb + (r - 245) * 64 + c4 * 4);
        }
        *(float4*)(xs + r * STR_ + c4 * 4) = val;
    }
    for (int idx = tid; idx < NS_ * 49; idx += NT2_) {
        int s = idx / 49, j = idx - s * 49;
        size_t off = ((size_t)(bv * NS_ + s) * NG_ + g) * 49 + j;
        bet[idx] = beta[off];
        gam[idx] = gamma[off];
    }
    __syncthreads();

    for (int r = tid; r < ROWS_; r += NT2_) {
        const float2* xr = (const float2*)(xs + r * STR_);
        float a0 = 0.f, a1 = 0.f;
        #pragma unroll
        for (int c = 0; c < 32; c++) { float2 x = xr[c]; a0 = fmaf(x.x, x.x, a0); a1 = fmaf(x.y, x.y, a1); }
        rsq[r] = a0 + a1;
    }
    __syncthreads();

    bool active = (tid < ROWS_);
    int it = tid / 7;
    int jt = tid - it * 7;

    if (active) {
        float acc[49];
        #pragma unroll
        for (int k = 0; k < 49; k++) acc[k] = 0.0f;

        const float2* A  = (const float2*)(xs + it * 7 * STR_);
        const float2* Bm = (const float2*)(xs + (245 + jt * 7) * STR_);
        #pragma unroll 1
        for (int c2 = 0; c2 < 32; c2++) {
            float2 a[7], bb[7];
            #pragma unroll
            for (int k = 0; k < 7; k++) a[k]  = A[k * (STR_ / 2) + c2];
            #pragma unroll
            for (int k = 0; k < 7; k++) bb[k] = Bm[k * (STR_ / 2) + c2];
            #pragma unroll
            for (int ii = 0; ii < 7; ii++)
                #pragma unroll
                for (int jj = 0; jj < 7; jj++) {
                    acc[ii * 7 + jj] = fmaf(a[ii].x, bb[jj].x, acc[ii * 7 + jj]);
                    acc[ii * 7 + jj] = fmaf(a[ii].y, bb[jj].y, acc[ii * 7 + jj]);
                }
        }

        float qsq[7];
        int jbase = jt * 7;
        #pragma unroll
        for (int jj = 0; jj < 7; jj++) qsq[jj] = rsq[245 + jbase + jj];
        #pragma unroll
        for (int ii = 0; ii < 7; ii++) {
            float ri = rsq[it * 7 + ii];
            #pragma unroll
            for (int jj = 0; jj < 7; jj++) {
                float d2 = ri + qsq[jj] - 2.0f * acc[ii * 7 + jj];
                acc[ii * 7 + jj] = multi_gauss(d2);
            }
        }

        if (it < 35) {
            int s = it / 7;
            int i0 = it * 7 - s * 49;
            const float* gs = gam + s * 49 + jbase;
            const float* bs = bet + s * 49 + i0;
            float partial = 0.0f;
            #pragma unroll
            for (int ii = 0; ii < 7; ii++) {
                float rowsum = 0.0f;
                #pragma unroll
                for (int jj = 0; jj < 7; jj++) rowsum = fmaf(acc[ii * 7 + jj], gs[jj], rowsum);
                partial = fmaf(bs[ii], rowsum, partial);
            }
            scr[tid] = partial;
        } else {
            int q0 = it * 7 - 245;
            int qt = tid - 245;
            #pragma unroll
            for (int s = 0; s < 5; s++) {
                const float* gs = gam + s * 49;
                float pq = 0.0f;
                #pragma unroll
                for (int ii = 0; ii < 7; ii++) {
                    float rowsum = 0.0f;
                    #pragma unroll
                    for (int jj = 0; jj < 7; jj++) rowsum = fmaf(acc[ii * 7 + jj], gs[jbase + jj], rowsum);
                    pq = fmaf(gs[q0 + ii], rowsum, pq);
                }
                scrq[s * 49 + qt] = pq;
            }
        }
    }
    __syncthreads();

    if (tid < 10) {
        int s = tid % 5;
        const float* src = (tid < 5) ? (scr + s * 49) : (scrq + s * 49);
        float acc2 = 0.f;
        #pragma unroll
        for (int k = 0; k < 49; k++) acc2 += src[k];
        red[tid] = acc2;
    }
    __syncthreads();

    if (tid < NS_) {
        int idx = (bv * NS_ + tid) * NG_ + g;
        g_p2[idx] = red[5 + tid] - 2.0f * red[tid];
    }
}

__global__ void k3_reduce(float* __restrict__ out) {
    int o = blockIdx.x * blockDim.x + threadIdx.x;
    if (o < B_ * NQ_ * NS_) {
        float s = 0.0f;
        #pragma unroll
        for (int g = 0; g < NG_; g++) s += g_p1[o * NG_ + g] + g_p2[o * NG_ + g];
        out[o] = 0.25f * s;
    }
}

extern "C" void kernel_launch(void* const* d_in, const int* in_sizes, int n_in,
                              void* d_out, int out_size) {
    const float* sup   = (const float*)d_in[0];
    const float* qry   = (const float*)d_in[1];
    const float* beta  = (const float*)d_in[2];
    const float* gamma = (const float*)d_in[3];
    float* out = (float*)d_out;

    const int smem2 = (ROWS_ * STR_ + 296 + 245 * 4 + 16) * (int)sizeof(float);
    static bool configured = false;
    if (!configured) {
        cudaFuncSetAttribute(k2_main, cudaFuncAttributeMaxDynamicSharedMemorySize, smem2);
        configured = true;
    }

    k1a_kss<<<B_ * NS_ * NG_, 64>>>(sup);
    k1b_bilinear<<<B_ * NS_ * NG_ * 5, 256>>>(beta);
    k2_main<<<B_ * NQ_ * NG_, NT2_, smem2>>>(sup, qry, beta, gamma);
    k3_reduce<<<(B_ * NQ_ * NS_ + 255) / 256, 256>>>(out);
}